// round 2
// baseline (speedup 1.0000x reference)
#include <cuda_runtime.h>
#include <cstdint>

#define DI __device__ __forceinline__

static constexpr int HDIM   = 1024;
static constexpr int BATCH  = 8192;
static constexpr int BM     = 128;   // batch rows per CTA
static constexpr int BN     = 32;    // gate cols per CTA (x6 gate blocks)
static constexpr int NTH    = 256;   // 8 warps: 4 (m) x 2 (n)
static constexpr int NSTAGE = 96;    // 32 input + 32 hx + 32 att K-stages

static constexpr int APITCH = 36;              // floats per smem row (32 + 4 pad)
static constexpr int ABYTES = BM * APITCH * 4; // 18432
static constexpr int BBLKF  = 32 * APITCH;     // floats per B gate-block (1152)
static constexpr int BBYTES = 4 * BBLKF * 4;   // 18432
static constexpr int BUFB   = ABYTES + BBYTES; // 36864
static constexpr int SMEMB  = 2 * BUFB;        // 73728

DI uint32_t f2tf(float x) {  // round-to-nearest tf32 (unbiased)
    uint32_t r;
    asm("cvt.rna.tf32.f32 %0, %1;" : "=r"(r) : "f"(x));
    return r;
}
DI float sigmf(float x) { return 1.0f / (1.0f + __expf(-x)); }

DI void mma8(float* d, const uint32_t* a, const uint32_t* b) {
    asm volatile(
        "mma.sync.aligned.m16n8k8.row.col.f32.tf32.tf32.f32 "
        "{%0,%1,%2,%3}, {%4,%5,%6,%7}, {%8,%9}, {%0,%1,%2,%3};"
        : "+f"(d[0]), "+f"(d[1]), "+f"(d[2]), "+f"(d[3])
        : "r"(a[0]), "r"(a[1]), "r"(a[2]), "r"(a[3]), "r"(b[0]), "r"(b[1]));
}

// ---- per-stage source selection -------------------------------------------
// stages 0..31 : A=input, B=wih  (4 gate blocks, accum c[0..3])
// stages 32..63: A=hx,    B=whh  (4 gate blocks, accum c[0..3])
// stages 64..95: A=att,   B=watt (2 att blocks,  accum c[4..5])
DI void ldg_stage(int s, int m0, int n0, int tid,
                  const float* __restrict__ inp, const float* __restrict__ hx,
                  const float* __restrict__ att, const float* __restrict__ wih,
                  const float* __restrict__ whh, const float* __restrict__ watt,
                  float4 rA[4], float4 rB[4], int& nb_out)
{
    const float *Ap, *Bp;
    int k0, nb;
    if (s < 32)      { Ap = inp; Bp = wih;  k0 = s * 32;        nb = 4; }
    else if (s < 64) { Ap = hx;  Bp = whh;  k0 = (s - 32) * 32; nb = 4; }
    else             { Ap = att; Bp = watt; k0 = (s - 64) * 32; nb = 2; }
    nb_out = nb;
    #pragma unroll
    for (int j = 0; j < 4; ++j) {                 // A: 128x32 -> 4 float4/thread
        int idx = tid + j * NTH;
        int r = idx >> 3, c4 = idx & 7;
        rA[j] = __ldg((const float4*)(Ap + (size_t)(m0 + r) * HDIM + k0 + c4 * 4));
    }
    #pragma unroll
    for (int j = 0; j < 4; ++j) {                 // B: nb x 32 x 32
        if (j < 2 || nb == 4) {
            int idx = tid + j * NTH;
            int blk = idx >> 8, rem = idx & 255;
            int r = rem >> 3, c4 = rem & 7;
            rB[j] = __ldg((const float4*)(Bp + (size_t)(blk * HDIM + n0 + r) * HDIM + k0 + c4 * 4));
        }
    }
}

DI void sts_stage(char* smem, int buf, int tid, int nb,
                  const float4 rA[4], const float4 rB[4])
{
    uint32_t* As = (uint32_t*)(smem + buf * BUFB);
    uint32_t* Bs = (uint32_t*)(smem + buf * BUFB + ABYTES);
    #pragma unroll
    for (int j = 0; j < 4; ++j) {
        int idx = tid + j * NTH;
        int r = idx >> 3, c4 = idx & 7;
        uint4 u = make_uint4(f2tf(rA[j].x), f2tf(rA[j].y), f2tf(rA[j].z), f2tf(rA[j].w));
        *(uint4*)(As + r * APITCH + c4 * 4) = u;
    }
    #pragma unroll
    for (int j = 0; j < 4; ++j) {
        if (j < 2 || nb == 4) {
            int idx = tid + j * NTH;
            int blk = idx >> 8, rem = idx & 255;
            int r = rem >> 3, c4 = rem & 7;
            uint4 u = make_uint4(f2tf(rB[j].x), f2tf(rB[j].y), f2tf(rB[j].z), f2tf(rB[j].w));
            *(uint4*)(Bs + blk * BBLKF + r * APITCH + c4 * 4) = u;
        }
    }
}

template <int NB, int CB>
DI void compute_stage(const char* smem, int buf, int wm, int wn, int lane,
                      float c[6][2][2][4])
{
    const uint32_t* As = (const uint32_t*)(smem + buf * BUFB);
    const uint32_t* Bs = (const uint32_t*)(smem + buf * BUFB + ABYTES);
    const int gid = lane >> 2, tig = lane & 3;
    #pragma unroll
    for (int k8 = 0; k8 < 4; ++k8) {
        uint32_t a[2][4];
        #pragma unroll
        for (int mf = 0; mf < 2; ++mf) {
            const uint32_t* p = As + (wm * 32 + mf * 16 + gid) * APITCH + k8 * 8 + tig;
            a[mf][0] = p[0];
            a[mf][1] = p[8 * APITCH];
            a[mf][2] = p[4];
            a[mf][3] = p[8 * APITCH + 4];
        }
        #pragma unroll
        for (int blk = 0; blk < NB; ++blk) {
            uint32_t b[2][2];
            #pragma unroll
            for (int nf = 0; nf < 2; ++nf) {
                const uint32_t* p = Bs + blk * BBLKF + (wn * 16 + nf * 8 + gid) * APITCH + k8 * 8 + tig;
                b[nf][0] = p[0];
                b[nf][1] = p[4];
            }
            #pragma unroll
            for (int mf = 0; mf < 2; ++mf)
                #pragma unroll
                for (int nf = 0; nf < 2; ++nf)
                    mma8(c[CB + blk][mf][nf], a[mf], b[nf]);
        }
    }
}

__global__ __launch_bounds__(NTH, 1)
void lstm_att_kernel(const float* __restrict__ inp, const float* __restrict__ hx,
                     const float* __restrict__ cx,  const float* __restrict__ att,
                     const float* __restrict__ wih, const float* __restrict__ whh,
                     const float* __restrict__ bih, const float* __restrict__ bhh,
                     const float* __restrict__ watt, const float* __restrict__ batt,
                     float* __restrict__ out)
{
    extern __shared__ char smem[];
    const int tid  = threadIdx.x;
    const int wid  = tid >> 5;
    const int lane = tid & 31;
    const int wm = wid >> 1, wn = wid & 1;
    const int n0 = blockIdx.x * BN;
    const int m0 = blockIdx.y * BM;

    float c[6][2][2][4];
    #pragma unroll
    for (int b = 0; b < 6; ++b)
        #pragma unroll
        for (int mf = 0; mf < 2; ++mf)
            #pragma unroll
            for (int nf = 0; nf < 2; ++nf)
                #pragma unroll
                for (int i = 0; i < 4; ++i) c[b][mf][nf][i] = 0.0f;

    float4 rA[4], rB[4];
    int nb;
    ldg_stage(0, m0, n0, tid, inp, hx, att, wih, whh, watt, rA, rB, nb);
    sts_stage(smem, 0, tid, nb, rA, rB);
    __syncthreads();

    for (int s = 1; s < NSTAGE; ++s) {
        int nbn;
        ldg_stage(s, m0, n0, tid, inp, hx, att, wih, whh, watt, rA, rB, nbn);
        if (s - 1 < 64) compute_stage<4, 0>(smem, (s - 1) & 1, wm, wn, lane, c);
        else            compute_stage<2, 4>(smem, (s - 1) & 1, wm, wn, lane, c);
        sts_stage(smem, s & 1, tid, nbn, rA, rB);
        __syncthreads();
    }
    compute_stage<2, 4>(smem, (NSTAGE - 1) & 1, wm, wn, lane, c);

    // ---- fused LSTM epilogue: all 6 gates for (row,col) live in this thread ----
    const int gid = lane >> 2, tig = lane & 3;
    const size_t cy_base = (size_t)BATCH * HDIM;
    #pragma unroll
    for (int mf = 0; mf < 2; ++mf) {
        #pragma unroll
        for (int i2 = 0; i2 < 2; ++i2) {
            const int row = m0 + wm * 32 + mf * 16 + gid + i2 * 8;
            #pragma unroll
            for (int nf = 0; nf < 2; ++nf) {
                const int col = n0 + wn * 16 + nf * 8 + tig * 2;
                float2 cx2 = __ldg((const float2*)(cx + (size_t)row * HDIM + col));
                float hyv[2], cyv[2];
                #pragma unroll
                for (int q = 0; q < 2; ++q) {
                    const int i = i2 * 2 + q;
                    const int n = col + q;
                    float gi  = c[0][mf][nf][i] + __ldg(bih + n)        + __ldg(bhh + n);
                    float gf  = c[1][mf][nf][i] + __ldg(bih + 1024 + n) + __ldg(bhh + 1024 + n);
                    float gc  = c[2][mf][nf][i] + __ldg(bih + 2048 + n) + __ldg(bhh + 2048 + n);
                    float go  = c[3][mf][nf][i] + __ldg(bih + 3072 + n) + __ldg(bhh + 3072 + n);
                    float gia = c[4][mf][nf][i] + __ldg(batt + n);
                    float gaa = c[5][mf][nf][i] + __ldg(batt + 1024 + n);
                    float i_  = sigmf(gi);
                    float f_  = sigmf(gf);
                    float c_  = tanhf(gc);
                    float o_  = sigmf(go);
                    float ia_ = sigmf(gia);
                    float aa_ = tanhf(gaa);
                    float cv  = f_ * ((q == 0) ? cx2.x : cx2.y) + i_ * c_ + ia_ * aa_;
                    cyv[q] = cv;
                    hyv[q] = o_ * tanhf(cv);
                }
                *(float2*)(out + (size_t)row * HDIM + col)           = make_float2(hyv[0], hyv[1]);
                *(float2*)(out + cy_base + (size_t)row * HDIM + col) = make_float2(cyv[0], cyv[1]);
            }
        }
    }
}

extern "C" void kernel_launch(void* const* d_in, const int* in_sizes, int n_in,
                              void* d_out, int out_size)
{
    (void)in_sizes; (void)n_in; (void)out_size;
    const float* inp  = (const float*)d_in[0];
    const float* hx   = (const float*)d_in[1];
    const float* cx   = (const float*)d_in[2];
    const float* att  = (const float*)d_in[3];
    const float* wih  = (const float*)d_in[4];
    const float* whh  = (const float*)d_in[5];
    const float* bih  = (const float*)d_in[6];
    const float* bhh  = (const float*)d_in[7];
    const float* watt = (const float*)d_in[8];
    const float* batt = (const float*)d_in[9];
    float* out = (float*)d_out;

    cudaFuncSetAttribute(lstm_att_kernel,
                         cudaFuncAttributeMaxDynamicSharedMemorySize, SMEMB);
    dim3 grid(HDIM / BN, BATCH / BM);  // n-tiles fastest => A reuse within a wave
    lstm_att_kernel<<<grid, NTH, SMEMB>>>(
        inp, hx, cx, att, wih, whh, bih, bhh, watt, batt, out);
}

// round 3
// speedup vs baseline: 1.2994x; 1.2994x over previous
#include <cuda_runtime.h>
#include <cstdint>

#define DI __device__ __forceinline__

static constexpr int HDIM   = 1024;
static constexpr int BATCH  = 8192;
static constexpr int BM     = 128;   // batch rows per CTA
static constexpr int BN     = 32;    // gate cols per CTA (x6 gate blocks)
static constexpr int NTH    = 256;   // 8 warps: 4 (m) x 2 (n)
static constexpr int NSTAGE = 96;    // 32 input + 32 hx + 32 att K-stages

// stage buffer: A 128x32 tf32 (16KB) + B 4x32x32 (16KB), 4-deep ring
static constexpr int ABYTES = BM * 128;        // 16384
static constexpr int BUFB   = ABYTES + 16384;  // 32768
static constexpr int SMEMB  = 4 * BUFB;        // 131072

// tf32-converted scratch (prepass output). Offsets in u32 elements.
static constexpr size_t OFF_INP  = 0;
static constexpr size_t OFF_HX   = 8388608;
static constexpr size_t OFF_ATT  = 16777216;
static constexpr size_t OFF_WIH  = 25165824;
static constexpr size_t OFF_WHH  = 29360128;
static constexpr size_t OFF_WATT = 33554432;
static constexpr size_t CVT_TOTAL = 35651584;   // ~142.6 MB

__device__ uint32_t g_cvt[CVT_TOTAL];

DI uint32_t f2tf(float x) {  // round-to-nearest tf32 (unbiased)
    uint32_t r;
    asm("cvt.rna.tf32.f32 %0, %1;" : "=r"(r) : "f"(x));
    return r;
}
DI float sigmf(float x) { return 1.0f / (1.0f + __expf(-x)); }

DI uint32_t smem_u32(const void* p) {
    uint32_t r;
    asm("{ .reg .u64 t; cvta.to.shared.u64 t, %1; cvt.u32.u64 %0, t; }" : "=r"(r) : "l"(p));
    return r;
}
DI void cp16(uint32_t sdst, const uint32_t* gsrc) {
    asm volatile("cp.async.cg.shared.global [%0], [%1], 16;" :: "r"(sdst), "l"(gsrc));
}
DI void cp_commit() { asm volatile("cp.async.commit_group;" ::: "memory"); }
template <int N>
DI void cp_wait() { asm volatile("cp.async.wait_group %0;" :: "n"(N) : "memory"); }

DI void ldsm4(uint32_t* r, uint32_t addr) {
    asm volatile("ldmatrix.sync.aligned.m8n8.x4.shared.b16 {%0,%1,%2,%3}, [%4];"
                 : "=r"(r[0]), "=r"(r[1]), "=r"(r[2]), "=r"(r[3]) : "r"(addr));
}
DI void mma8(float* d, const uint32_t* a, const uint32_t* b) {
    asm volatile(
        "mma.sync.aligned.m16n8k8.row.col.f32.tf32.tf32.f32 "
        "{%0,%1,%2,%3}, {%4,%5,%6,%7}, {%8,%9}, {%0,%1,%2,%3};"
        : "+f"(d[0]), "+f"(d[1]), "+f"(d[2]), "+f"(d[3])
        : "r"(a[0]), "r"(a[1]), "r"(a[2]), "r"(a[3]), "r"(b[0]), "r"(b[1]));
}

// ---- prepass: fp32 -> tf32(RNA) bulk convert ----
__global__ void cvt4_kernel(const float4* __restrict__ src, uint4* __restrict__ dst, int n4) {
    int i = blockIdx.x * blockDim.x + threadIdx.x;
    int stride = gridDim.x * blockDim.x;
    for (; i < n4; i += stride) {
        float4 v = __ldg(src + i);
        dst[i] = make_uint4(f2tf(v.x), f2tf(v.y), f2tf(v.z), f2tf(v.w));
    }
}

// ---- main kernel ----
// stages 0..31 : A=input, B=wih  (4 gate blocks, accum c[0..3])
// stages 32..63: A=hx,    B=whh  (4 gate blocks, accum c[0..3])
// stages 64..95: A=att,   B=watt (2 att blocks,  accum c[4..5])
DI void issue_stage(int s, int m0, int n0, int tid, uint32_t sbase) {
    int seg = s >> 5;
    int k0  = (s & 31) << 5;
    int nb  = (seg == 2) ? 2 : 4;
    const uint32_t* Ag;
    const uint32_t* Bg;
    if (seg == 0)      { Ag = g_cvt + OFF_INP; Bg = g_cvt + OFF_WIH;  }
    else if (seg == 1) { Ag = g_cvt + OFF_HX;  Bg = g_cvt + OFF_WHH;  }
    else               { Ag = g_cvt + OFF_ATT; Bg = g_cvt + OFF_WATT; }
    const uint32_t buf = sbase + (s & 3) * BUFB;
    #pragma unroll
    for (int j = 0; j < 4; ++j) {               // A: 1024 16B chunks
        int idx = tid + j * NTH;
        int r = idx >> 3, cc = idx & 7;
        uint32_t sdst = buf + r * 128 + ((cc ^ (r & 7)) << 4);
        cp16(sdst, Ag + (size_t)(m0 + r) * HDIM + k0 + cc * 4);
    }
    #pragma unroll
    for (int j = 0; j < 4; ++j) {               // B: nb x 256 chunks
        int idx = tid + j * NTH;
        int blk = idx >> 8, rem = idx & 255;
        if (blk < nb) {
            int r = rem >> 3, cc = rem & 7;
            uint32_t sdst = buf + ABYTES + blk * 4096 + r * 128 + ((cc ^ (r & 7)) << 4);
            cp16(sdst, Bg + (size_t)(blk * HDIM + n0 + r) * HDIM + k0 + cc * 4);
        }
    }
    cp_commit();
}

template <int NB, int CB>
DI void compute_stage(uint32_t sbuf, int wm, int wn, int lane, float c[6][2][2][4]) {
    const uint32_t Ab = sbuf;
    const uint32_t Bb = sbuf + ABYTES;
    // ldmatrix address geometry (see fragment mapping of m16n8k8 tf32)
    const int rowA  = wm * 32 + (lane & 15);
    const int ahi   = (lane >> 4) & 1;
    const int rowB  = wn * 16 + (lane & 7) + ((lane & 16) >> 1);
    const int bhi   = (lane >> 3) & 1;
    const uint32_t aoff0 = Ab + rowA * 128;
    const uint32_t aoff1 = Ab + (rowA + 16) * 128;
    const int ax = rowA & 7;                  // (rowA+16)&7 == ax
    const uint32_t boff = rowB * 128;
    const int bx = rowB & 7;
    #pragma unroll
    for (int k8 = 0; k8 < 4; ++k8) {
        uint32_t a0[4], a1[4];
        const int ca = k8 * 2 + ahi;
        ldsm4(a0, aoff0 + ((ca ^ ax) << 4));
        ldsm4(a1, aoff1 + ((ca ^ ax) << 4));
        const int cb = k8 * 2 + bhi;
        #pragma unroll
        for (int blk = 0; blk < NB; ++blk) {
            uint32_t b[4];
            ldsm4(b, Bb + blk * 4096 + boff + ((cb ^ bx) << 4));
            mma8(c[CB + blk][0][0], a0, b);
            mma8(c[CB + blk][0][1], a0, b + 2);
            mma8(c[CB + blk][1][0], a1, b);
            mma8(c[CB + blk][1][1], a1, b + 2);
        }
    }
}

__global__ __launch_bounds__(NTH, 1)
void lstm_att_kernel(const float* __restrict__ cx,
                     const float* __restrict__ bih, const float* __restrict__ bhh,
                     const float* __restrict__ batt,
                     float* __restrict__ out)
{
    extern __shared__ char smem[];
    const int tid  = threadIdx.x;
    const int wid  = tid >> 5;
    const int lane = tid & 31;
    const int wm = wid >> 1, wn = wid & 1;
    const int n0 = blockIdx.x * BN;
    const int m0 = blockIdx.y * BM;
    const uint32_t sbase = smem_u32(smem);

    float c[6][2][2][4];
    #pragma unroll
    for (int b = 0; b < 6; ++b)
        #pragma unroll
        for (int mf = 0; mf < 2; ++mf)
            #pragma unroll
            for (int nf = 0; nf < 2; ++nf)
                #pragma unroll
                for (int i = 0; i < 4; ++i) c[b][mf][nf][i] = 0.0f;

    issue_stage(0, m0, n0, tid, sbase);
    issue_stage(1, m0, n0, tid, sbase);
    issue_stage(2, m0, n0, tid, sbase);

    for (int s = 0; s < NSTAGE; ++s) {
        cp_wait<2>();
        __syncthreads();
        if (s + 3 < NSTAGE) issue_stage(s + 3, m0, n0, tid, sbase);
        const uint32_t buf = sbase + (s & 3) * BUFB;
        if (s < 64) compute_stage<4, 0>(buf, wm, wn, lane, c);
        else        compute_stage<2, 4>(buf, wm, wn, lane, c);
    }

    // ---- fused LSTM epilogue: all 6 gates for (row,col) live in this thread ----
    const int gid = lane >> 2, tig = lane & 3;
    const size_t cy_base = (size_t)BATCH * HDIM;
    #pragma unroll
    for (int mf = 0; mf < 2; ++mf) {
        #pragma unroll
        for (int i2 = 0; i2 < 2; ++i2) {
            const int row = m0 + wm * 32 + mf * 16 + gid + i2 * 8;
            #pragma unroll
            for (int nf = 0; nf < 2; ++nf) {
                const int col = n0 + wn * 16 + nf * 8 + tig * 2;
                float2 cx2 = __ldg((const float2*)(cx + (size_t)row * HDIM + col));
                float hyv[2], cyv[2];
                #pragma unroll
                for (int q = 0; q < 2; ++q) {
                    const int i = i2 * 2 + q;
                    const int n = col + q;
                    float gi  = c[0][mf][nf][i] + __ldg(bih + n)        + __ldg(bhh + n);
                    float gf  = c[1][mf][nf][i] + __ldg(bih + 1024 + n) + __ldg(bhh + 1024 + n);
                    float gc  = c[2][mf][nf][i] + __ldg(bih + 2048 + n) + __ldg(bhh + 2048 + n);
                    float go  = c[3][mf][nf][i] + __ldg(bih + 3072 + n) + __ldg(bhh + 3072 + n);
                    float gia = c[4][mf][nf][i] + __ldg(batt + n);
                    float gaa = c[5][mf][nf][i] + __ldg(batt + 1024 + n);
                    float i_  = sigmf(gi);
                    float f_  = sigmf(gf);
                    float c_  = tanhf(gc);
                    float o_  = sigmf(go);
                    float ia_ = sigmf(gia);
                    float aa_ = tanhf(gaa);
                    float cv  = f_ * ((q == 0) ? cx2.x : cx2.y) + i_ * c_ + ia_ * aa_;
                    cyv[q] = cv;
                    hyv[q] = o_ * tanhf(cv);
                }
                *(float2*)(out + (size_t)row * HDIM + col)           = make_float2(hyv[0], hyv[1]);
                *(float2*)(out + cy_base + (size_t)row * HDIM + col) = make_float2(cyv[0], cyv[1]);
            }
        }
    }
}

extern "C" void kernel_launch(void* const* d_in, const int* in_sizes, int n_in,
                              void* d_out, int out_size)
{
    (void)in_sizes; (void)n_in; (void)out_size;
    const float* inp  = (const float*)d_in[0];
    const float* hx   = (const float*)d_in[1];
    const float* cx   = (const float*)d_in[2];
    const float* att  = (const float*)d_in[3];
    const float* wih  = (const float*)d_in[4];
    const float* whh  = (const float*)d_in[5];
    const float* bih  = (const float*)d_in[6];
    const float* bhh  = (const float*)d_in[7];
    const float* watt = (const float*)d_in[8];
    const float* batt = (const float*)d_in[9];
    float* out = (float*)d_out;

    uint32_t* g;
    cudaGetSymbolAddress((void**)&g, g_cvt);

    const int BIG = BATCH * HDIM / 4;       // 2,097,152 float4s
    const int W4  = 4 * HDIM * HDIM / 4;    // 1,048,576
    const int W2  = 2 * HDIM * HDIM / 4;    //   524,288
    cvt4_kernel<<<1024, 256>>>((const float4*)inp,  (uint4*)(g + OFF_INP),  BIG);
    cvt4_kernel<<<1024, 256>>>((const float4*)hx,   (uint4*)(g + OFF_HX),   BIG);
    cvt4_kernel<<<1024, 256>>>((const float4*)att,  (uint4*)(g + OFF_ATT),  BIG);
    cvt4_kernel<<<1024, 256>>>((const float4*)wih,  (uint4*)(g + OFF_WIH),  W4);
    cvt4_kernel<<<1024, 256>>>((const float4*)whh,  (uint4*)(g + OFF_WHH),  W4);
    cvt4_kernel<<<1024, 256>>>((const float4*)watt, (uint4*)(g + OFF_WATT), W2);

    cudaFuncSetAttribute(lstm_att_kernel,
                         cudaFuncAttributeMaxDynamicSharedMemorySize, SMEMB);
    dim3 grid(HDIM / BN, BATCH / BM);  // n-tiles fastest => A/L2 reuse within a wave
    lstm_att_kernel<<<grid, NTH, SMEMB>>>(cx, bih, bhh, batt, out);
}